// round 2
// baseline (speedup 1.0000x reference)
#include <cuda_runtime.h>
#include <math.h>
#include <stdint.h>

#define NLEV 12
#define PRIME1 2654435761u
#define PRIME2 805459861u
#define HMASK ((1u << 21) - 1u)

struct LevelSpec {
    float    scale[NLEV];
    unsigned off[NLEV];
    unsigned res1[NLEV];    // res + 1 (dense stride base)
    unsigned hashed[NLEV];  // 0/1
};

__device__ float g_S[8192];     // per-line mean weighted L1
__device__ float g_part[256];   // conf-kernel block partials

typedef unsigned long long u64;

// ---------- packed f32x2 helpers (sm_103a FFMA2: 2x FP32 throughput) ----------
__device__ __forceinline__ u64 bcast_f32x2(float v) {
    u64 d;
    asm("mov.b64 %0, {%1, %1};" : "=l"(d) : "f"(v));
    return d;
}
__device__ __forceinline__ void fma_f32x2(u64& acc, u64 a, u64 b) {
    asm("fma.rn.f32x2 %0, %1, %2, %0;" : "+l"(acc) : "l"(a), "l"(b));
}
__device__ __forceinline__ float2 unpack_f32x2(u64 v) {
    float2 r;
    asm("mov.b64 {%0, %1}, %2;" : "=f"(r.x), "=f"(r.y) : "l"(v));
    return r;
}

// 24 -> 64(relu) -> 1 MLP. Weights live in shared:
//   s_w1: 24 rows x 32 f32x2 pairs (pair j = hidden units 2j,2j+1), 16B aligned
//   s_b1: 32 f32x2 pairs, s_w2: 64 floats
__device__ __forceinline__ float tiny_mlp(const float* feat, const u64* s_w1,
                                          const u64* s_b1, const float* s_w2,
                                          float b2v) {
    u64 acc[32];
#pragma unroll
    for (int j = 0; j < 32; j++) acc[j] = s_b1[j];
#pragma unroll
    for (int k = 0; k < 24; k++) {
        u64 bf = bcast_f32x2(feat[k]);
        const ulonglong2* row = (const ulonglong2*)(s_w1 + k * 32);
#pragma unroll
        for (int j = 0; j < 16; j++) {
            ulonglong2 wv = row[j];       // LDS.128: two f32x2 weight pairs
            fma_f32x2(acc[2 * j],     bf, wv.x);
            fma_f32x2(acc[2 * j + 1], bf, wv.y);
        }
    }
    float op = b2v;
#pragma unroll
    for (int j = 0; j < 32; j++) {
        float2 h = unpack_f32x2(acc[j]);
        op += fmaxf(h.x, 0.0f) * s_w2[2 * j];
        op += fmaxf(h.y, 0.0f) * s_w2[2 * j + 1];
    }
    return op;
}

// ========================== opacity path: B*P 3-D points ==========================
__global__ void __launch_bounds__(128, 4)
opacity_kernel(const float* __restrict__ pts, const float* __restrict__ gt,
               const float* __restrict__ table,
               const float* __restrict__ w1, const float* __restrict__ b1,
               const float* __restrict__ w2, const float* __restrict__ b2,
               LevelSpec sp, int P) {
    __shared__ __align__(16) u64 s_w1[768];
    __shared__ u64   s_b1[32];
    __shared__ float s_w2[64];
    __shared__ float s_red[128];

    const int tid = threadIdx.x;
    const u64* w1d = (const u64*)w1;
    for (int i = tid; i < 768; i += 128) s_w1[i] = w1d[i];
    if (tid < 32) s_b1[tid] = ((const u64*)b1)[tid];
    if (tid < 64) s_w2[tid] = w2[tid];
    const float b2v = __ldg(b2);
    __syncthreads();

    const int b = blockIdx.x;
    const float*  ptb = pts + (size_t)b * P * 3;
    const float*  gtb = gt + (size_t)b * P;
    const float2* tb  = (const float2*)table;

    float lsum = 0.0f;
    for (int p = tid; p < P; p += 128) {
        float u0 = (ptb[3 * p + 0] + 1.0f) * 0.5f;
        float u1 = (ptb[3 * p + 1] + 1.0f) * 0.5f;
        float u2 = (ptb[3 * p + 2] + 1.0f) * 0.5f;

        float feat[24];
#pragma unroll
        for (int l = 0; l < NLEV; l++) {
            const float s = sp.scale[l];
            float px = u0 * s + 0.5f, py = u1 * s + 0.5f, pz = u2 * s + 0.5f;
            float fx = floorf(px), fy = floorf(py), fz = floorf(pz);
            float ax = px - fx, ay = py - fy, az = pz - fz;
            unsigned ix = (unsigned)fx, iy = (unsigned)fy, iz = (unsigned)fz;

            unsigned id[8];
            if (sp.hashed[l]) {
                unsigned hy0 = iy * PRIME1, hy1 = hy0 + PRIME1;
                unsigned hz0 = iz * PRIME2, hz1 = hz0 + PRIME2;
                unsigned a0 = ix ^ hy0, a1 = (ix + 1u) ^ hy0;
                unsigned a2 = ix ^ hy1, a3 = (ix + 1u) ^ hy1;
                id[0] = (a0 ^ hz0) & HMASK; id[1] = (a1 ^ hz0) & HMASK;
                id[2] = (a2 ^ hz0) & HMASK; id[3] = (a3 ^ hz0) & HMASK;
                id[4] = (a0 ^ hz1) & HMASK; id[5] = (a1 ^ hz1) & HMASK;
                id[6] = (a2 ^ hz1) & HMASK; id[7] = (a3 ^ hz1) & HMASK;
            } else {
                unsigned s1 = sp.res1[l], s2 = s1 * s1;
                unsigned base = ix + iy * s1 + iz * s2;
                id[0] = base;           id[1] = base + 1u;
                id[2] = base + s1;      id[3] = base + s1 + 1u;
                id[4] = base + s2;      id[5] = base + s2 + 1u;
                id[6] = base + s2 + s1; id[7] = base + s2 + s1 + 1u;
            }
            const unsigned off = sp.off[l];
            float2 v0 = __ldg(tb + off + id[0]);
            float2 v1 = __ldg(tb + off + id[1]);
            float2 v2 = __ldg(tb + off + id[2]);
            float2 v3 = __ldg(tb + off + id[3]);
            float2 v4 = __ldg(tb + off + id[4]);
            float2 v5 = __ldg(tb + off + id[5]);
            float2 v6 = __ldg(tb + off + id[6]);
            float2 v7 = __ldg(tb + off + id[7]);

            float wx0 = 1.0f - ax, wy0 = 1.0f - ay, wz0 = 1.0f - az;
            float w00 = wx0 * wy0, w10 = ax * wy0, w01 = wx0 * ay, w11 = ax * ay;
            float c0 = w00 * wz0, c1 = w10 * wz0, c2 = w01 * wz0, c3 = w11 * wz0;
            float c4 = w00 * az,  c5 = w10 * az,  c6 = w01 * az,  c7 = w11 * az;

            float fxo = c0 * v0.x; fxo += c1 * v1.x; fxo += c2 * v2.x; fxo += c3 * v3.x;
            fxo += c4 * v4.x; fxo += c5 * v5.x; fxo += c6 * v6.x; fxo += c7 * v7.x;
            float fyo = c0 * v0.y; fyo += c1 * v1.y; fyo += c2 * v2.y; fyo += c3 * v3.y;
            fyo += c4 * v4.y; fyo += c5 * v5.y; fyo += c6 * v6.y; fyo += c7 * v7.y;
            feat[2 * l] = fxo;
            feat[2 * l + 1] = fyo;
        }

        float op = tiny_mlp(feat, s_w1, s_b1, s_w2, b2v);
        float lw = (p < 500) ? (4.0f / 3.0f) : (2.0f / 3.0f);
        lsum += fabsf(op - __ldg(gtb + p)) * lw;
    }

    s_red[tid] = lsum;
    __syncthreads();
#pragma unroll
    for (int st = 64; st > 0; st >>= 1) {
        if (tid < st) s_red[tid] += s_red[tid + st];
        __syncthreads();
    }
    if (tid == 0) g_S[b] = s_red[0] * (1.0f / (float)P);
}

// ========================== confidence path: B 2-D lines ==========================
__global__ void __launch_bounds__(128, 4)
conf_kernel(const float* __restrict__ line, const float* __restrict__ table,
            const float* __restrict__ w1, const float* __restrict__ b1,
            const float* __restrict__ w2, const float* __restrict__ b2,
            LevelSpec sp, int B) {
    __shared__ __align__(16) u64 s_w1[768];
    __shared__ u64   s_b1[32];
    __shared__ float s_w2[64];
    __shared__ float s_red[128];

    const int tid = threadIdx.x;
    const u64* w1d = (const u64*)w1;
    for (int i = tid; i < 768; i += 128) s_w1[i] = w1d[i];
    if (tid < 32) s_b1[tid] = ((const u64*)b1)[tid];
    if (tid < 64) s_w2[tid] = w2[tid];
    const float b2v = __ldg(b2);
    __syncthreads();

    const int i = blockIdx.x * 128 + tid;
    float val = 0.0f;
    if (i < B) {
        const float2* tb = (const float2*)table;
        float u0 = (__ldg(line + 2 * i) + 1.0f) * 0.5f;
        float u1 = (__ldg(line + 2 * i + 1) + 1.0f) * 0.5f;

        float feat[24];
#pragma unroll
        for (int l = 0; l < NLEV; l++) {
            const float s = sp.scale[l];
            float px = u0 * s + 0.5f, py = u1 * s + 0.5f;
            float fx = floorf(px), fy = floorf(py);
            float ax = px - fx, ay = py - fy;
            unsigned ix = (unsigned)fx, iy = (unsigned)fy;

            unsigned id[4];
            if (sp.hashed[l]) {
                unsigned hy0 = iy * PRIME1, hy1 = hy0 + PRIME1;
                id[0] = (ix ^ hy0) & HMASK; id[1] = ((ix + 1u) ^ hy0) & HMASK;
                id[2] = (ix ^ hy1) & HMASK; id[3] = ((ix + 1u) ^ hy1) & HMASK;
            } else {
                unsigned s1 = sp.res1[l];
                unsigned base = ix + iy * s1;
                id[0] = base;      id[1] = base + 1u;
                id[2] = base + s1; id[3] = base + s1 + 1u;
            }
            const unsigned off = sp.off[l];
            float2 v0 = __ldg(tb + off + id[0]);
            float2 v1 = __ldg(tb + off + id[1]);
            float2 v2 = __ldg(tb + off + id[2]);
            float2 v3 = __ldg(tb + off + id[3]);

            float wx0 = 1.0f - ax, wy0 = 1.0f - ay;
            float c0 = wx0 * wy0, c1 = ax * wy0, c2 = wx0 * ay, c3 = ax * ay;
            float fxo = c0 * v0.x; fxo += c1 * v1.x; fxo += c2 * v2.x; fxo += c3 * v3.x;
            float fyo = c0 * v0.y; fyo += c1 * v1.y; fyo += c2 * v2.y; fyo += c3 * v3.y;
            feat[2 * l] = fxo;
            feat[2 * l + 1] = fyo;
        }
        float conf = tiny_mlp(feat, s_w1, s_b1, s_w2, b2v);
        val = expf(-conf) * g_S[i] + conf;
    }

    s_red[tid] = val;
    __syncthreads();
#pragma unroll
    for (int st = 64; st > 0; st >>= 1) {
        if (tid < st) s_red[tid] += s_red[tid + st];
        __syncthreads();
    }
    if (tid == 0) g_part[blockIdx.x] = s_red[0];
}

__global__ void final_kernel(float* out, int nb, float invB) {
    __shared__ float sr[256];
    int t = threadIdx.x;
    sr[t] = (t < nb) ? g_part[t] : 0.0f;
    __syncthreads();
#pragma unroll
    for (int st = 128; st > 0; st >>= 1) {
        if (t < st) sr[t] += sr[t + st];
        __syncthreads();
    }
    if (t == 0) out[0] = sr[0] * invB;
}

// ---------- host: replicate _level_specs exactly (float64 math) ----------
static void make_specs(int D, LevelSpec* sp) {
    double f = pow(8192.0 / 16.0, 1.0 / 11.0);
    long long offset = 0;
    for (int l = 0; l < NLEV; l++) {
        double scale = 16.0 * pow(f, (double)l) - 1.0;
        long long res = (long long)ceil(scale) + 1;
        long long dense = 1;
        for (int d = 0; d < D; d++) dense *= (res + 1);
        long long params = dense;
        if (params > (1LL << 21)) params = (1LL << 21);
        params = ((params + 7) / 8) * 8;
        sp->scale[l]  = (float)scale;
        sp->off[l]    = (unsigned)offset;
        sp->res1[l]   = (unsigned)(res + 1);
        sp->hashed[l] = (dense > (1LL << 21)) ? 1u : 0u;
        offset += params;
    }
}

extern "C" void kernel_launch(void* const* d_in, const int* in_sizes, int n_in,
                              void* d_out, int out_size) {
    const float* line  = (const float*)d_in[0];
    const float* pts   = (const float*)d_in[1];
    const float* gt    = (const float*)d_in[2];
    const float* tconf = (const float*)d_in[3];
    const float* w1c   = (const float*)d_in[4];
    const float* b1c   = (const float*)d_in[5];
    const float* w2c   = (const float*)d_in[6];
    const float* b2c   = (const float*)d_in[7];
    const float* top   = (const float*)d_in[8];
    const float* w1o   = (const float*)d_in[9];
    const float* b1o   = (const float*)d_in[10];
    const float* w2o   = (const float*)d_in[11];
    const float* b2o   = (const float*)d_in[12];

    int B = in_sizes[0] / 2;
    int P = in_sizes[1] / (3 * B);

    LevelSpec sp3, sp2;
    make_specs(3, &sp3);
    make_specs(2, &sp2);

    opacity_kernel<<<B, 128>>>(pts, gt, top, w1o, b1o, w2o, b2o, sp3, P);

    int nb = (B + 127) / 128;
    if (nb > 256) nb = 256;  // B=4096 -> 32 blocks
    conf_kernel<<<nb, 128>>>(line, tconf, w1c, b1c, w2c, b2c, sp2, B);
    final_kernel<<<1, 256>>>((float*)d_out, nb, 1.0f / (float)B);
}

// round 3
// speedup vs baseline: 1.0388x; 1.0388x over previous
#include <cuda_runtime.h>
#include <math.h>
#include <stdint.h>

#define NLEV 12
#define PRIME1 2654435761u
#define PRIME2 805459861u
#define HMASK ((1u << 21) - 1u)

struct LevelSpec {
    float    scale[NLEV];
    unsigned off[NLEV];
    unsigned res1[NLEV];    // res + 1 (dense stride base)
    unsigned hashed[NLEV];  // 0/1
};

__device__ float g_S[8192];     // per-line mean weighted L1
__device__ float g_part[256];   // conf-kernel block partials

typedef unsigned long long u64;

// MLP weights in constant memory (filled per-launch by async D2D memcpy nodes).
// w1 layout: u64 index k*32+j = packed f32x2 of hidden units (2j, 2j+1), input k.
__constant__ u64   c_w1o[768];
__constant__ u64   c_b1o[32];
__constant__ float c_w2o[64];
__constant__ float c_b2o[1];
__constant__ u64   c_w1c[768];
__constant__ u64   c_b1c[32];
__constant__ float c_w2c[64];
__constant__ float c_b2c[1];

// ---------- packed f32x2 helpers (sm_103a FFMA2: 2x FP32 throughput) ----------
__device__ __forceinline__ u64 bcast_f32x2(float v) {
    u64 d;
    asm("mov.b64 %0, {%1, %1};" : "=l"(d) : "f"(v));
    return d;
}
__device__ __forceinline__ void fma_f32x2(u64& acc, u64 a, u64 b) {
    asm("fma.rn.f32x2 %0, %1, %2, %0;" : "+l"(acc) : "l"(a), "l"(b));
}
__device__ __forceinline__ float2 unpack_f32x2(u64 v) {
    float2 r;
    asm("mov.b64 {%0, %1}, %2;" : "=f"(r.x), "=f"(r.y) : "l"(v));
    return r;
}

// 24 -> 64(relu) -> 1 MLP, weights from constant memory (OP selects set).
template <bool OP>
__device__ __forceinline__ float tiny_mlp(const float* feat) {
    u64 acc[32];
#pragma unroll
    for (int j = 0; j < 32; j++) acc[j] = OP ? c_b1o[j] : c_b1c[j];
#pragma unroll
    for (int k = 0; k < 24; k++) {
        u64 bf = bcast_f32x2(feat[k]);
#pragma unroll
        for (int j = 0; j < 32; j++) {
            u64 wv = OP ? c_w1o[k * 32 + j] : c_w1c[k * 32 + j];
            fma_f32x2(acc[j], bf, wv);
        }
    }
    float out = OP ? c_b2o[0] : c_b2c[0];
#pragma unroll
    for (int j = 0; j < 32; j++) {
        float2 h = unpack_f32x2(acc[j]);
        out += fmaxf(h.x, 0.0f) * (OP ? c_w2o[2 * j]     : c_w2c[2 * j]);
        out += fmaxf(h.y, 0.0f) * (OP ? c_w2o[2 * j + 1] : c_w2c[2 * j + 1]);
    }
    return out;
}

// ========================== opacity path: B*P 3-D points ==========================
__global__ void __launch_bounds__(128, 4)
opacity_kernel(const float* __restrict__ pts, const float* __restrict__ gt,
               const float* __restrict__ table, LevelSpec sp, int P) {
    __shared__ __align__(16) float s_pts[3072];  // up to 1024 points * 3
    __shared__ float s_red[128];

    const int tid = threadIdx.x;
    const int b = blockIdx.x;
    const float*  ptb = pts + (size_t)b * P * 3;
    const float*  gtb = gt + (size_t)b * P;
    const float2* tb  = (const float2*)table;

    // coalesced stage of this line's point strip into shared
    {
        int n4 = (3 * P) / 4;
        const float4* src4 = (const float4*)ptb;
        for (int i = tid; i < n4; i += 128) ((float4*)s_pts)[i] = src4[i];
        for (int i = 4 * n4 + tid; i < 3 * P; i += 128) s_pts[i] = ptb[i];
    }
    __syncthreads();

    float lsum = 0.0f;
    for (int p = tid; p < P; p += 128) {
        float u0 = (s_pts[3 * p + 0] + 1.0f) * 0.5f;
        float u1 = (s_pts[3 * p + 1] + 1.0f) * 0.5f;
        float u2 = (s_pts[3 * p + 2] + 1.0f) * 0.5f;

        float feat[24];
#pragma unroll
        for (int l = 0; l < NLEV; l++) {
            const float s = sp.scale[l];
            float px = u0 * s + 0.5f, py = u1 * s + 0.5f, pz = u2 * s + 0.5f;
            float fx = floorf(px), fy = floorf(py), fz = floorf(pz);
            float ax = px - fx, ay = py - fy, az = pz - fz;
            unsigned ix = (unsigned)fx, iy = (unsigned)fy, iz = (unsigned)fz;

            unsigned id[8];
            if (sp.hashed[l]) {
                unsigned hy0 = iy * PRIME1, hy1 = hy0 + PRIME1;
                unsigned hz0 = iz * PRIME2, hz1 = hz0 + PRIME2;
                unsigned a0 = ix ^ hy0, a1 = (ix + 1u) ^ hy0;
                unsigned a2 = ix ^ hy1, a3 = (ix + 1u) ^ hy1;
                id[0] = (a0 ^ hz0) & HMASK; id[1] = (a1 ^ hz0) & HMASK;
                id[2] = (a2 ^ hz0) & HMASK; id[3] = (a3 ^ hz0) & HMASK;
                id[4] = (a0 ^ hz1) & HMASK; id[5] = (a1 ^ hz1) & HMASK;
                id[6] = (a2 ^ hz1) & HMASK; id[7] = (a3 ^ hz1) & HMASK;
            } else {
                unsigned s1 = sp.res1[l], s2 = s1 * s1;
                unsigned base = ix + iy * s1 + iz * s2;
                id[0] = base;           id[1] = base + 1u;
                id[2] = base + s1;      id[3] = base + s1 + 1u;
                id[4] = base + s2;      id[5] = base + s2 + 1u;
                id[6] = base + s2 + s1; id[7] = base + s2 + s1 + 1u;
            }
            const unsigned off = sp.off[l];
            float2 v0 = __ldg(tb + off + id[0]);
            float2 v1 = __ldg(tb + off + id[1]);
            float2 v2 = __ldg(tb + off + id[2]);
            float2 v3 = __ldg(tb + off + id[3]);
            float2 v4 = __ldg(tb + off + id[4]);
            float2 v5 = __ldg(tb + off + id[5]);
            float2 v6 = __ldg(tb + off + id[6]);
            float2 v7 = __ldg(tb + off + id[7]);

            float wx0 = 1.0f - ax, wy0 = 1.0f - ay, wz0 = 1.0f - az;
            float w00 = wx0 * wy0, w10 = ax * wy0, w01 = wx0 * ay, w11 = ax * ay;
            float c0 = w00 * wz0, c1 = w10 * wz0, c2 = w01 * wz0, c3 = w11 * wz0;
            float c4 = w00 * az,  c5 = w10 * az,  c6 = w01 * az,  c7 = w11 * az;

            float fxo = c0 * v0.x; fxo += c1 * v1.x; fxo += c2 * v2.x; fxo += c3 * v3.x;
            fxo += c4 * v4.x; fxo += c5 * v5.x; fxo += c6 * v6.x; fxo += c7 * v7.x;
            float fyo = c0 * v0.y; fyo += c1 * v1.y; fyo += c2 * v2.y; fyo += c3 * v3.y;
            fyo += c4 * v4.y; fyo += c5 * v5.y; fyo += c6 * v6.y; fyo += c7 * v7.y;
            feat[2 * l] = fxo;
            feat[2 * l + 1] = fyo;
        }

        float op = tiny_mlp<true>(feat);
        float lw = (p < 500) ? (4.0f / 3.0f) : (2.0f / 3.0f);
        lsum += fabsf(op - __ldg(gtb + p)) * lw;
    }

    s_red[tid] = lsum;
    __syncthreads();
#pragma unroll
    for (int st = 64; st > 0; st >>= 1) {
        if (tid < st) s_red[tid] += s_red[tid + st];
        __syncthreads();
    }
    if (tid == 0) g_S[b] = s_red[0] * (1.0f / (float)P);
}

// ========================== confidence path: B 2-D lines ==========================
__global__ void __launch_bounds__(128, 4)
conf_kernel(const float* __restrict__ line, const float* __restrict__ table,
            LevelSpec sp, int B) {
    __shared__ float s_red[128];
    const int tid = threadIdx.x;

    const int i = blockIdx.x * 128 + tid;
    float val = 0.0f;
    if (i < B) {
        const float2* tb = (const float2*)table;
        float u0 = (__ldg(line + 2 * i) + 1.0f) * 0.5f;
        float u1 = (__ldg(line + 2 * i + 1) + 1.0f) * 0.5f;

        float feat[24];
#pragma unroll
        for (int l = 0; l < NLEV; l++) {
            const float s = sp.scale[l];
            float px = u0 * s + 0.5f, py = u1 * s + 0.5f;
            float fx = floorf(px), fy = floorf(py);
            float ax = px - fx, ay = py - fy;
            unsigned ix = (unsigned)fx, iy = (unsigned)fy;

            unsigned id[4];
            if (sp.hashed[l]) {
                unsigned hy0 = iy * PRIME1, hy1 = hy0 + PRIME1;
                id[0] = (ix ^ hy0) & HMASK; id[1] = ((ix + 1u) ^ hy0) & HMASK;
                id[2] = (ix ^ hy1) & HMASK; id[3] = ((ix + 1u) ^ hy1) & HMASK;
            } else {
                unsigned s1 = sp.res1[l];
                unsigned base = ix + iy * s1;
                id[0] = base;      id[1] = base + 1u;
                id[2] = base + s1; id[3] = base + s1 + 1u;
            }
            const unsigned off = sp.off[l];
            float2 v0 = __ldg(tb + off + id[0]);
            float2 v1 = __ldg(tb + off + id[1]);
            float2 v2 = __ldg(tb + off + id[2]);
            float2 v3 = __ldg(tb + off + id[3]);

            float wx0 = 1.0f - ax, wy0 = 1.0f - ay;
            float c0 = wx0 * wy0, c1 = ax * wy0, c2 = wx0 * ay, c3 = ax * ay;
            float fxo = c0 * v0.x; fxo += c1 * v1.x; fxo += c2 * v2.x; fxo += c3 * v3.x;
            float fyo = c0 * v0.y; fyo += c1 * v1.y; fyo += c2 * v2.y; fyo += c3 * v3.y;
            feat[2 * l] = fxo;
            feat[2 * l + 1] = fyo;
        }
        float conf = tiny_mlp<false>(feat);
        val = expf(-conf) * g_S[i] + conf;
    }

    s_red[tid] = val;
    __syncthreads();
#pragma unroll
    for (int st = 64; st > 0; st >>= 1) {
        if (tid < st) s_red[tid] += s_red[tid + st];
        __syncthreads();
    }
    if (tid == 0) g_part[blockIdx.x] = s_red[0];
}

__global__ void final_kernel(float* out, int nb, float invB) {
    __shared__ float sr[256];
    int t = threadIdx.x;
    sr[t] = (t < nb) ? g_part[t] : 0.0f;
    __syncthreads();
#pragma unroll
    for (int st = 128; st > 0; st >>= 1) {
        if (t < st) sr[t] += sr[t + st];
        __syncthreads();
    }
    if (t == 0) out[0] = sr[0] * invB;
}

// ---------- host: replicate _level_specs exactly (float64 math) ----------
static void make_specs(int D, LevelSpec* sp) {
    double f = pow(8192.0 / 16.0, 1.0 / 11.0);
    long long offset = 0;
    for (int l = 0; l < NLEV; l++) {
        double scale = 16.0 * pow(f, (double)l) - 1.0;
        long long res = (long long)ceil(scale) + 1;
        long long dense = 1;
        for (int d = 0; d < D; d++) dense *= (res + 1);
        long long params = dense;
        if (params > (1LL << 21)) params = (1LL << 21);
        params = ((params + 7) / 8) * 8;
        sp->scale[l]  = (float)scale;
        sp->off[l]    = (unsigned)offset;
        sp->res1[l]   = (unsigned)(res + 1);
        sp->hashed[l] = (dense > (1LL << 21)) ? 1u : 0u;
        offset += params;
    }
}

extern "C" void kernel_launch(void* const* d_in, const int* in_sizes, int n_in,
                              void* d_out, int out_size) {
    const float* line  = (const float*)d_in[0];
    const float* pts   = (const float*)d_in[1];
    const float* gt    = (const float*)d_in[2];
    const float* tconf = (const float*)d_in[3];
    const float* w1c   = (const float*)d_in[4];
    const float* b1c   = (const float*)d_in[5];
    const float* w2c   = (const float*)d_in[6];
    const float* b2c   = (const float*)d_in[7];
    const float* top   = (const float*)d_in[8];
    const float* w1o   = (const float*)d_in[9];
    const float* b1o   = (const float*)d_in[10];
    const float* w2o   = (const float*)d_in[11];
    const float* b2o   = (const float*)d_in[12];

    int B = in_sizes[0] / 2;
    int P = in_sizes[1] / (3 * B);

    LevelSpec sp3, sp2;
    make_specs(3, &sp3);
    make_specs(2, &sp2);

    // weights -> constant memory (D2D memcpy nodes; graph-capturable)
    cudaMemcpyToSymbolAsync(c_w1o, w1o, 1536 * sizeof(float), 0, cudaMemcpyDeviceToDevice);
    cudaMemcpyToSymbolAsync(c_b1o, b1o, 64 * sizeof(float),   0, cudaMemcpyDeviceToDevice);
    cudaMemcpyToSymbolAsync(c_w2o, w2o, 64 * sizeof(float),   0, cudaMemcpyDeviceToDevice);
    cudaMemcpyToSymbolAsync(c_b2o, b2o, sizeof(float),        0, cudaMemcpyDeviceToDevice);
    cudaMemcpyToSymbolAsync(c_w1c, w1c, 1536 * sizeof(float), 0, cudaMemcpyDeviceToDevice);
    cudaMemcpyToSymbolAsync(c_b1c, b1c, 64 * sizeof(float),   0, cudaMemcpyDeviceToDevice);
    cudaMemcpyToSymbolAsync(c_w2c, w2c, 64 * sizeof(float),   0, cudaMemcpyDeviceToDevice);
    cudaMemcpyToSymbolAsync(c_b2c, b2c, sizeof(float),        0, cudaMemcpyDeviceToDevice);

    opacity_kernel<<<B, 128>>>(pts, gt, top, sp3, P);

    int nb = (B + 127) / 128;
    if (nb > 256) nb = 256;  // B=4096 -> 32 blocks
    conf_kernel<<<nb, 128>>>(line, tconf, sp2, B);
    final_kernel<<<1, 256>>>((float*)d_out, nb, 1.0f / (float)B);
}